// round 8
// baseline (speedup 1.0000x reference)
#include <cuda_runtime.h>
#include <cuda_bf16.h>
#include <cuda_fp8.h>
#include <cstdint>

// EDMLoss = mean((Xhat-X)^2) + 0.25*memloss - 0.1*mean(Dhat)
// memloss = 2*(sum||h||^2 + sum_row min_k(||m_k||^2 - 2 h.m_k)) / (B*D*T)
// GEMM [32768x256]@[256x512] via mma.sync m16n8k32 e4m3 (fp8): pairs of
// consecutive d packed as 16-bit "units" -> identical fragment geometry to
// the validated bf16 16816 kernel. ||h||^2 / ||m||^2 exact fp32.

namespace {
constexpr int Bn = 64, Dn = 256, Tn = 512, Kn = 512;
constexpr int Un = 128;                       // d-pair units
constexpr int N_REC  = 64 * 8 * 512;
constexpr int N_DHAT = 64 * 512;

constexpr uint32_t AP    = 528;               // A' pitch bytes (256 units*2B + 16)
constexpr uint32_t BP    = 1040;              // B' pitch bytes (512 units*2B + 16)
constexpr uint32_t SA    = 0;                 // A': 128 * 528 = 67584
constexpr uint32_t SB    = 67584;             // B': 128 * 1040 = 133120
constexpr uint32_t SMNS  = 200704;            // 512 f32 ||m||^2
constexpr uint32_t SRMIN = 202752;            // 2 groups * 256 f32 row mins
constexpr uint32_t SRED  = 204800;            // 8 f32 | 8 doubles at +64
constexpr uint32_t SMEMT = 204928;
}

__device__ double g_acc[4];      // 0 rec, 1 minscore, 2 dhat, 3 sum H^2 (zero-invariant)
__device__ unsigned g_ticket;
__device__ float  g_mnorm[Kn];
__device__ __align__(16) uint16_t g_Bu[(size_t)Un * Kn];   // fp8-pair units [u][cw]

__device__ __forceinline__ uint32_t smem_u32(const void* p) {
    uint32_t a;
    asm("{ .reg .u64 t; cvta.to.shared.u64 t, %1; cvt.u32.u64 %0, t; }" : "=r"(a) : "l"(p));
    return a;
}
__device__ __forceinline__ void ldsm4t(uint32_t* r, uint32_t addr) {
    asm volatile("ldmatrix.sync.aligned.m8n8.x4.trans.shared.b16 {%0,%1,%2,%3}, [%4];"
                 : "=r"(r[0]), "=r"(r[1]), "=r"(r[2]), "=r"(r[3]) : "r"(addr));
}
__device__ __forceinline__ void mma_fp8(float* c, const uint32_t* a, const uint32_t* b) {
    asm volatile("mma.sync.aligned.m16n8k32.row.col.f32.e4m3.e4m3.f32 "
                 "{%0,%1,%2,%3}, {%4,%5,%6,%7}, {%8,%9}, {%0,%1,%2,%3};"
                 : "+f"(c[0]), "+f"(c[1]), "+f"(c[2]), "+f"(c[3])
                 : "r"(a[0]), "r"(a[1]), "r"(a[2]), "r"(a[3]), "r"(b[0]), "r"(b[1]));
}
__device__ __forceinline__ uint32_t f2e4m3(float v) {
    return (uint32_t)__nv_cvt_float_to_fp8(v, __NV_SATFINITE, __NV_E4M3);
}

// ---- prep: M -> fp8 pair units + exact mnorm (blocks 0-1), rec (2-257), dhat (258-289)
__global__ __launch_bounds__(256) void k_prep(const float* __restrict__ M,
                                              const float* __restrict__ Xhat,
                                              const float* __restrict__ X,
                                              const float* __restrict__ Dh) {
    const int blk = blockIdx.x;
    if (blk < 2) {
        int k = blk * 256 + threadIdx.x;
        float s = 0.f;
        #pragma unroll 4
        for (int u = 0; u < Un; ++u) {
            float v0 = M[(size_t)(2 * u)     * Kn + k];
            float v1 = M[(size_t)(2 * u + 1) * Kn + k];
            s = fmaf(v0, v0, fmaf(v1, v1, s));
            g_Bu[(size_t)u * Kn + k] = (uint16_t)(f2e4m3(v0) | (f2e4m3(v1) << 8));
        }
        g_mnorm[k] = s;
        return;
    }
    int which, n, b0, nb;
    const float* a; const float* bp;
    if (blk < 258) { which = 0; a = Xhat; bp = X; n = N_REC;  b0 = 2;   nb = 256; }
    else           { which = 2; a = Dh;   bp = 0; n = N_DHAT; b0 = 258; nb = 32;  }
    float s = 0.f;
    for (int i = (blk - b0) * 256 + threadIdx.x; i < n; i += nb * 256) {
        if (which == 0) { float d = a[i] - bp[i]; s = fmaf(d, d, s); }
        else            { s += a[i]; }
    }
    #pragma unroll
    for (int o = 16; o; o >>= 1) s += __shfl_down_sync(0xffffffffu, s, o);
    __shared__ float ws[8];
    int lane = threadIdx.x & 31, w = threadIdx.x >> 5;
    if (!lane) ws[w] = s;
    __syncthreads();
    if (threadIdx.x == 0) {
        float t = 0.f;
        #pragma unroll
        for (int i = 0; i < 8; ++i) t += ws[i];
        atomicAdd(&g_acc[which], (double)t);
    }
}

// ---- main fp8 GEMM + min epilogue: 256 rows x 512 cols per CTA, 256 threads ----
__global__ __launch_bounds__(256, 1) void k_mma(const float* __restrict__ H, float* out) {
    extern __shared__ char sm[];
    const uint32_t sb = smem_u32(sm);
    const int tid = threadIdx.x, w = tid >> 5, ln = tid & 31;
    const int row0 = blockIdx.x * 256;
    const int b = row0 >> 9, t0 = row0 & 511;          // t0 in {0, 256}

    ((float*)(sm + SMNS))[tid]       = g_mnorm[tid];
    ((float*)(sm + SMNS))[tid + 256] = g_mnorm[tid + 256];

    // Load whole B' (128 rows x 1024B) via cp.async: 8192 16B segments.
    {
        const size_t gb = __cvta_generic_to_global((const void*)g_Bu);
        #pragma unroll
        for (int i = 0; i < 32; ++i) {
            int seg = tid + 256 * i;                   // 0..8191
            int u = seg >> 6, s = seg & 63;
            uint32_t dst = sb + SB + u * BP + s * 16;
            size_t   src = gb + (size_t)u * 1024 + s * 16;
            asm volatile("cp.async.cg.shared.global [%0], [%1], 16;" :: "r"(dst), "l"(src));
        }
        asm volatile("cp.async.commit_group;" ::: "memory");
    }

    // Stage A': H rows 2u,2u+1 -> fp8 pair units [u][t]; accumulate sum(H^2).
    float sq = 0.f;
    const float* Hp = H + (size_t)b * Dn * Tn + t0;
    #pragma unroll
    for (int i = 0; i < 32; ++i) {
        int idx = tid + 256 * i;                       // 0..8191
        int u = idx >> 6, tg = idx & 63;               // t = tg*4
        const float* p0 = Hp + (size_t)(2 * u) * Tn + tg * 4;
        float4 v0 = *(const float4*)p0;
        float4 v1 = *(const float4*)(p0 + Tn);
        sq = fmaf(v0.x, v0.x, fmaf(v0.y, v0.y, fmaf(v0.z, v0.z, fmaf(v0.w, v0.w, sq))));
        sq = fmaf(v1.x, v1.x, fmaf(v1.y, v1.y, fmaf(v1.z, v1.z, fmaf(v1.w, v1.w, sq))));
        uint32_t lo = (f2e4m3(v0.x) | (f2e4m3(v1.x) << 8)) |
                      ((f2e4m3(v0.y) | (f2e4m3(v1.y) << 8)) << 16);
        uint32_t hi = (f2e4m3(v0.z) | (f2e4m3(v1.z) << 8)) |
                      ((f2e4m3(v0.w) | (f2e4m3(v1.w) << 8)) << 16);
        uint32_t a = sb + SA + u * AP + tg * 8;
        asm volatile("st.shared.v2.b32 [%0], {%1,%2};" :: "r"(a), "r"(lo), "r"(hi) : "memory");
    }
    #pragma unroll
    for (int o = 16; o; o >>= 1) sq += __shfl_down_sync(0xffffffffu, sq, o);
    if (!ln) ((float*)(sm + SRED))[w] = sq;

    asm volatile("cp.async.wait_group 0;" ::: "memory");
    __syncthreads();                                   // the only barrier before epilogue

    // 8 warps: 4 (m=t) x 2 (n=cw). Warp tile per 64-cw chunk: 64 rows x 32 cols.
    const int wm  = (w & 3) * 64;
    const int wn  = (w >> 2) * 32;
    const int s1  = ((ln >> 3) & 1) * 8;
    const int s2  = (ln >> 4) * 8;
    const int r8  = ln & 7;
    const float* mns = (const float*)(sm + SMNS);

    float rm[8];
    #pragma unroll
    for (int i = 0; i < 8; ++i) rm[i] = 3.4e38f;

    #pragma unroll
    for (int c = 0; c < 8; ++c) {
        float acc[4][4][4];
        #pragma unroll
        for (int mf = 0; mf < 4; ++mf)
            #pragma unroll
            for (int nf = 0; nf < 4; ++nf)
                #pragma unroll
                for (int j = 0; j < 4; ++j) acc[mf][nf][j] = 0.f;

        #pragma unroll
        for (int ks = 0; ks < 8; ++ks) {               // 16 units (=32 d) per step
            const int u0 = ks * 16;
            uint32_t af[4][4], bf[2][4];
            #pragma unroll
            for (int np = 0; np < 2; ++np)
                ldsm4t(bf[np], sb + SB + (u0 + s1 + r8) * BP + (c * 64 + wn + np * 16 + s2) * 2);
            #pragma unroll
            for (int mf = 0; mf < 4; ++mf)
                ldsm4t(af[mf], sb + SA + (u0 + s2 + r8) * AP + (wm + mf * 16 + s1) * 2);
            #pragma unroll
            for (int mf = 0; mf < 4; ++mf)
                #pragma unroll
                for (int nf = 0; nf < 4; ++nf)
                    mma_fp8(acc[mf][nf], af[mf], &bf[nf >> 1][(nf & 1) * 2]);
        }

        // epilogue: score = ||m||^2 - 2*dot, running min per row
        const int cb = c * 64 + wn + 2 * (ln & 3);
        #pragma unroll
        for (int nf = 0; nf < 4; ++nf) {
            float m0 = mns[cb + nf * 8], m1 = mns[cb + nf * 8 + 1];
            #pragma unroll
            for (int mf = 0; mf < 4; ++mf) {
                rm[mf * 2]     = fminf(rm[mf * 2],
                    fminf(fmaf(-2.f, acc[mf][nf][0], m0), fmaf(-2.f, acc[mf][nf][1], m1)));
                rm[mf * 2 + 1] = fminf(rm[mf * 2 + 1],
                    fminf(fmaf(-2.f, acc[mf][nf][2], m0), fmaf(-2.f, acc[mf][nf][3], m1)));
            }
        }
    }

    // combine 4 lanes sharing each row
    #pragma unroll
    for (int o = 1; o < 4; o <<= 1) {
        #pragma unroll
        for (int i = 0; i < 8; ++i) rm[i] = fminf(rm[i], __shfl_xor_sync(0xffffffffu, rm[i], o));
    }
    if ((ln & 3) == 0) {
        float* rmin = (float*)(sm + SRMIN) + (w >> 2) * 256;   // per n-group array
        int r = wm + (ln >> 2);
        #pragma unroll
        for (int mf = 0; mf < 4; ++mf) {
            rmin[r + mf * 16]     = rm[mf * 2];
            rmin[r + mf * 16 + 8] = rm[mf * 2 + 1];
        }
    }
    __syncthreads();

    {   // all 256 threads: combine n-groups, sum rows
        const float* r0 = (const float*)(sm + SRMIN);
        double s = (double)fminf(r0[tid], r0[tid + 256]);
        #pragma unroll
        for (int o = 16; o; o >>= 1) s += __shfl_down_sync(0xffffffffu, s, o);
        if (!ln) ((double*)(sm + SRED + 64))[w] = s;
    }
    __syncthreads();

    if (tid == 0) {
        const double* dr = (const double*)(sm + SRED + 64);
        double ms = 0.0;
        #pragma unroll
        for (int i = 0; i < 8; ++i) ms += dr[i];
        atomicAdd(&g_acc[1], ms);
        const float* ws = (const float*)(sm + SRED);
        double hs = 0.0;
        #pragma unroll
        for (int i = 0; i < 8; ++i) hs += (double)ws[i];
        atomicAdd(&g_acc[3], hs);

        __threadfence();
        unsigned old = atomicAdd(&g_ticket, 1u);
        if (old == gridDim.x - 1) {
            __threadfence();
            double a0 = *(volatile double*)&g_acc[0];
            double a1 = *(volatile double*)&g_acc[1];
            double a2 = *(volatile double*)&g_acc[2];
            double a3 = *(volatile double*)&g_acc[3];
            double mem = 2.0 * (a3 + a1) / (double)((size_t)Bn * Dn * Tn);
            out[0] = (float)(a0 / (double)N_REC + 0.25 * mem - 0.1 * a2 / (double)N_DHAT);
            g_acc[0] = 0.0; g_acc[1] = 0.0; g_acc[2] = 0.0; g_acc[3] = 0.0;
            g_ticket = 0u;
            __threadfence();
        }
    }
}

extern "C" void kernel_launch(void* const* d_in, const int* in_sizes, int n_in,
                              void* d_out, int out_size) {
    (void)in_sizes; (void)n_in; (void)out_size;
    const float* Xhat = (const float*)d_in[0];
    const float* X    = (const float*)d_in[1];
    const float* H    = (const float*)d_in[2];
    const float* M    = (const float*)d_in[3];
    const float* Dh   = (const float*)d_in[4];

    cudaFuncSetAttribute(k_mma, cudaFuncAttributeMaxDynamicSharedMemorySize, SMEMT);

    k_prep<<<290, 256>>>(M, Xhat, X, Dh);
    k_mma<<<128, 256, SMEMT>>>(H, (float*)d_out);
}

// round 9
// speedup vs baseline: 3.4255x; 3.4255x over previous
#include <cuda_runtime.h>
#include <cuda_bf16.h>
#include <cstdint>

// EDMLoss = mean((Xhat-X)^2) + 0.25*memloss - 0.1*mean(Dhat)
// memloss = 2*(sum||h||^2 + sum_row min_k(||m_k||^2 - 2 h.m_k)) / (B*D*T)
// GEMM [32768x256]@[256x512] via mma.sync bf16.
// 256 CTAs x 256 threads, 2 CTAs/SM (cross-CTA latency overlap).
// CTA tile 128 rows x 512 cols; B streamed in 64-col chunks (single buffer).

namespace {
constexpr int Bn = 64, Dn = 256, Tn = 512, Kn = 512;
constexpr int N_REC  = 64 * 8 * 512;
constexpr int N_DHAT = 64 * 512;

constexpr uint32_t AP    = 272;                 // A pitch bytes (128 bf16 + 16 pad)
constexpr uint32_t BP    = 144;                 // B pitch bytes (64 bf16 + 16 pad)
constexpr uint32_t SA    = 0;                   // A: 256*272 = 69632
constexpr uint32_t SB    = 69632;               // B: 256*144 = 36864
constexpr uint32_t SMNS  = 106496;              // 512 f32 ||m||^2
constexpr uint32_t SRMIN = 108544;              // 2 groups * 128 f32 row mins
constexpr uint32_t SRED  = 109568;              // 8 f32 | 4 doubles at +64
constexpr uint32_t SMEMT = 109696;              // 107.1 KB -> 2 CTAs/SM
}

__device__ double g_acc[4];      // 0 rec, 1 minscore, 2 dhat, 3 sum H^2 (zero-invariant)
__device__ unsigned g_ticket;
__device__ float  g_mnorm[Kn];
__device__ __align__(16) __nv_bfloat16 g_Mc[(size_t)Dn * Kn];

__device__ __forceinline__ uint32_t smem_u32(const void* p) {
    uint32_t a;
    asm("{ .reg .u64 t; cvta.to.shared.u64 t, %1; cvt.u32.u64 %0, t; }" : "=r"(a) : "l"(p));
    return a;
}
__device__ __forceinline__ void ldsm4t(uint32_t* r, uint32_t addr) {
    asm volatile("ldmatrix.sync.aligned.m8n8.x4.trans.shared.b16 {%0,%1,%2,%3}, [%4];"
                 : "=r"(r[0]), "=r"(r[1]), "=r"(r[2]), "=r"(r[3]) : "r"(addr));
}
__device__ __forceinline__ void mma16816(float* c, const uint32_t* a, const uint32_t* b) {
    asm volatile("mma.sync.aligned.m16n8k16.row.col.f32.bf16.bf16.f32 "
                 "{%0,%1,%2,%3}, {%4,%5,%6,%7}, {%8,%9}, {%0,%1,%2,%3};"
                 : "+f"(c[0]), "+f"(c[1]), "+f"(c[2]), "+f"(c[3])
                 : "r"(a[0]), "r"(a[1]), "r"(a[2]), "r"(a[3]), "r"(b[0]), "r"(b[1]));
}

// ---- prep: M convert + mnorm (blocks 0-1), rec (2-257), dhat (258-289) ----
__global__ __launch_bounds__(256) void k_prep(const float* __restrict__ M,
                                              const float* __restrict__ Xhat,
                                              const float* __restrict__ X,
                                              const float* __restrict__ Dh) {
    const int blk = blockIdx.x;
    if (blk < 2) {
        int k = blk * 256 + threadIdx.x;
        float s = 0.f;
        #pragma unroll 8
        for (int d = 0; d < Dn; ++d) {
            float v = M[(size_t)d * Kn + k];
            g_Mc[(size_t)d * Kn + k] = __float2bfloat16(v);
            s = fmaf(v, v, s);
        }
        g_mnorm[k] = s;
        return;
    }
    int which, n, b0, nb;
    const float* a; const float* bp;
    if (blk < 258) { which = 0; a = Xhat; bp = X; n = N_REC;  b0 = 2;   nb = 256; }
    else           { which = 2; a = Dh;   bp = 0; n = N_DHAT; b0 = 258; nb = 32;  }
    float s = 0.f;
    for (int i = (blk - b0) * 256 + threadIdx.x; i < n; i += nb * 256) {
        if (which == 0) { float d = a[i] - bp[i]; s = fmaf(d, d, s); }
        else            { s += a[i]; }
    }
    #pragma unroll
    for (int o = 16; o; o >>= 1) s += __shfl_down_sync(0xffffffffu, s, o);
    __shared__ float ws[8];
    int lane = threadIdx.x & 31, w = threadIdx.x >> 5;
    if (!lane) ws[w] = s;
    __syncthreads();
    if (threadIdx.x == 0) {
        float t = 0.f;
        #pragma unroll
        for (int i = 0; i < 8; ++i) t += ws[i];
        atomicAdd(&g_acc[which], (double)t);
    }
}

// ---- main GEMM + min epilogue: 128 rows x 512 cols per CTA, 2 CTAs/SM ----
__global__ __launch_bounds__(256, 2) void k_mma(const float* __restrict__ H, float* out) {
    extern __shared__ char sm[];
    const uint32_t sb = smem_u32(sm);
    const int tid = threadIdx.x, w = tid >> 5, ln = tid & 31;
    const int row0 = blockIdx.x * 128;
    const int b = row0 >> 9, t0 = row0 & 511;

    ((float*)(sm + SMNS))[tid]       = g_mnorm[tid];
    ((float*)(sm + SMNS))[tid + 256] = g_mnorm[tid + 256];

    const size_t gmc = __cvta_generic_to_global((const void*)g_Mc);
    auto cp_chunk = [&](int c) {                        // 64-col chunk: 256 rows * 128B
        #pragma unroll
        for (int i = 0; i < 8; ++i) {
            int u = tid + 256 * i;                      // 0..2047 16B units
            int d = u >> 3, seg = u & 7;
            uint32_t dst = sb + SB + d * BP + seg * 16;
            size_t   src = gmc + (size_t)d * 1024 + (size_t)c * 128 + seg * 16;
            asm volatile("cp.async.cg.shared.global [%0], [%1], 16;" :: "r"(dst), "l"(src));
        }
        asm volatile("cp.async.commit_group;" ::: "memory");
    };
    cp_chunk(0);

    // Stage A: H[b][d][t0..t0+127] fp32 -> bf16 smem [d][t]; accumulate sum(H^2).
    float sq = 0.f;
    const float* Hp = H + (size_t)b * Dn * Tn + t0;
    #pragma unroll
    for (int i = 0; i < 32; ++i) {
        int d = i * 8 + w;
        float4 v = *(const float4*)(Hp + (size_t)d * Tn + ln * 4);
        sq = fmaf(v.x, v.x, fmaf(v.y, v.y, fmaf(v.z, v.z, fmaf(v.w, v.w, sq))));
        __nv_bfloat162 p0 = __floats2bfloat162_rn(v.x, v.y);
        __nv_bfloat162 p1 = __floats2bfloat162_rn(v.z, v.w);
        uint32_t a = sb + SA + d * AP + ln * 8;
        asm volatile("st.shared.v2.b32 [%0], {%1,%2};"
                     :: "r"(a), "r"(*(uint32_t*)&p0), "r"(*(uint32_t*)&p1) : "memory");
    }
    #pragma unroll
    for (int o = 16; o; o >>= 1) sq += __shfl_down_sync(0xffffffffu, sq, o);
    if (!ln) ((float*)(sm + SRED))[w] = sq;

    // 8 warps: 4 (m) x 2 (n). Warp tile per 64-col chunk: 32 rows x 32 cols.
    const int wm  = (w & 3) * 32;
    const int wn  = (w >> 2) * 32;
    const int s1  = ((ln >> 3) & 1) * 8;
    const int s2  = (ln >> 4) * 8;
    const int r8  = ln & 7;
    const float* mns = (const float*)(sm + SMNS);

    float rm[4] = {3.4e38f, 3.4e38f, 3.4e38f, 3.4e38f};

    #pragma unroll 1
    for (int c = 0; c < 8; ++c) {
        asm volatile("cp.async.wait_group 0;" ::: "memory");   // chunk c resident
        __syncthreads();

        float acc[2][4][4];
        #pragma unroll
        for (int mf = 0; mf < 2; ++mf)
            #pragma unroll
            for (int nf = 0; nf < 4; ++nf)
                #pragma unroll
                for (int j = 0; j < 4; ++j) acc[mf][nf][j] = 0.f;

        #pragma unroll
        for (int ks = 0; ks < 16; ++ks) {
            const int d0 = ks * 16;
            uint32_t af[2][4], bf[2][4];
            #pragma unroll
            for (int np = 0; np < 2; ++np)
                ldsm4t(bf[np], sb + SB + (d0 + s1 + r8) * BP + (wn + np * 16 + s2) * 2);
            #pragma unroll
            for (int mf = 0; mf < 2; ++mf)
                ldsm4t(af[mf], sb + SA + (d0 + s2 + r8) * AP + (wm + mf * 16 + s1) * 2);
            #pragma unroll
            for (int mf = 0; mf < 2; ++mf)
                #pragma unroll
                for (int nf = 0; nf < 4; ++nf)
                    mma16816(acc[mf][nf], af[mf], &bf[nf >> 1][(nf & 1) * 2]);
        }

        __syncthreads();                    // all warps done reading B buffer
        if (c < 7) cp_chunk(c + 1);

        // epilogue: score = ||m||^2 - 2*dot, running min per row
        const int cb = c * 64 + wn + 2 * (ln & 3);
        #pragma unroll
        for (int nf = 0; nf < 4; ++nf) {
            float m0 = mns[cb + nf * 8], m1 = mns[cb + nf * 8 + 1];
            rm[0] = fminf(rm[0], fminf(fmaf(-2.f, acc[0][nf][0], m0), fmaf(-2.f, acc[0][nf][1], m1)));
            rm[1] = fminf(rm[1], fminf(fmaf(-2.f, acc[0][nf][2], m0), fmaf(-2.f, acc[0][nf][3], m1)));
            rm[2] = fminf(rm[2], fminf(fmaf(-2.f, acc[1][nf][0], m0), fmaf(-2.f, acc[1][nf][1], m1)));
            rm[3] = fminf(rm[3], fminf(fmaf(-2.f, acc[1][nf][2], m0), fmaf(-2.f, acc[1][nf][3], m1)));
        }
    }

    // combine 4 lanes sharing each row
    #pragma unroll
    for (int o = 1; o < 4; o <<= 1) {
        #pragma unroll
        for (int i = 0; i < 4; ++i) rm[i] = fminf(rm[i], __shfl_xor_sync(0xffffffffu, rm[i], o));
    }
    if ((ln & 3) == 0) {
        float* rmin = (float*)(sm + SRMIN) + (w >> 2) * 128;   // per n-group array
        int r = wm + (ln >> 2);
        rmin[r] = rm[0]; rmin[r + 8] = rm[1]; rmin[r + 16] = rm[2]; rmin[r + 24] = rm[3];
    }
    __syncthreads();

    if (tid < 128) {
        const float* r0 = (const float*)(sm + SRMIN);
        double s = (double)fminf(r0[tid], r0[tid + 128]);
        #pragma unroll
        for (int o = 16; o; o >>= 1) s += __shfl_down_sync(0xffffffffu, s, o);
        if (!ln) ((double*)(sm + SRED + 64))[w] = s;
    }
    __syncthreads();

    if (tid == 0) {
        const double* dr = (const double*)(sm + SRED + 64);
        atomicAdd(&g_acc[1], dr[0] + dr[1] + dr[2] + dr[3]);
        const float* ws = (const float*)(sm + SRED);
        double hs = 0.0;
        #pragma unroll
        for (int i = 0; i < 8; ++i) hs += (double)ws[i];
        atomicAdd(&g_acc[3], hs);

        __threadfence();
        unsigned old = atomicAdd(&g_ticket, 1u);
        if (old == gridDim.x - 1) {
            __threadfence();
            double a0 = *(volatile double*)&g_acc[0];
            double a1 = *(volatile double*)&g_acc[1];
            double a2 = *(volatile double*)&g_acc[2];
            double a3 = *(volatile double*)&g_acc[3];
            double mem = 2.0 * (a3 + a1) / (double)((size_t)Bn * Dn * Tn);
            out[0] = (float)(a0 / (double)N_REC + 0.25 * mem - 0.1 * a2 / (double)N_DHAT);
            g_acc[0] = 0.0; g_acc[1] = 0.0; g_acc[2] = 0.0; g_acc[3] = 0.0;
            g_ticket = 0u;
            __threadfence();
        }
    }
}

extern "C" void kernel_launch(void* const* d_in, const int* in_sizes, int n_in,
                              void* d_out, int out_size) {
    (void)in_sizes; (void)n_in; (void)out_size;
    const float* Xhat = (const float*)d_in[0];
    const float* X    = (const float*)d_in[1];
    const float* H    = (const float*)d_in[2];
    const float* M    = (const float*)d_in[3];
    const float* Dh   = (const float*)d_in[4];

    cudaFuncSetAttribute(k_mma, cudaFuncAttributeMaxDynamicSharedMemorySize, SMEMT);

    k_prep<<<290, 256>>>(M, Xhat, X, Dh);
    k_mma<<<256, 256, SMEMT>>>(H, (float*)d_out);
}

// round 10
// speedup vs baseline: 4.3851x; 1.2801x over previous
#include <cuda_runtime.h>
#include <cuda_bf16.h>
#include <cstdint>

// EDMLoss = mean((Xhat-X)^2) + 0.25*memloss - 0.1*mean(Dhat)
// memloss = 2*(sum||h||^2 + sum_row min_k(||m_k||^2 - 2 h.m_k)) / (B*D*T)
// GEMM [32768x256]@[256x512] via mma.sync bf16 (structural floor ~512 MAC/cyc/SM).
// k_prep: M->bf16 + ||m||^2 only (16 blocks).
// k_mma : 148 CTAs = 128 GEMM CTAs (256 rows x 512 cols, R7 config) +
//         20 reduction CTAs (rec/dhat) on otherwise-idle SMs. Ticketed finalize.

namespace {
constexpr int Bn = 64, Dn = 256, Tn = 512, Kn = 512;
constexpr int N_REC  = 64 * 8 * 512;
constexpr int N_DHAT = 64 * 512;

constexpr uint32_t AP    = 528;                 // A pitch bytes (256 bf16 + 16 pad)
constexpr uint32_t BP    = 144;                 // B pitch bytes (64 bf16 + 16 pad)
constexpr uint32_t SA    = 0;                   // A: 256*528 = 135168
constexpr uint32_t SB0   = 135168;              // B buf0: 256*144 = 36864
constexpr uint32_t SB1   = 172032;              // B buf1
constexpr uint32_t SMNS  = 208896;              // 512 f32 ||m||^2
constexpr uint32_t SRMIN = 210944;              // 2 groups * 256 f32 row mins
constexpr uint32_t SRED  = 212992;              // 8 f32 | 8 doubles at +64
constexpr uint32_t SMEMT = 213120;
}

__device__ double g_acc[4];      // 0 rec, 1 minscore, 2 dhat, 3 sum H^2 (zero-invariant)
__device__ unsigned g_ticket;
__device__ float  g_mnorm[Kn];
__device__ __align__(16) __nv_bfloat16 g_Mc[(size_t)Dn * Kn];

__device__ __forceinline__ uint32_t smem_u32(const void* p) {
    uint32_t a;
    asm("{ .reg .u64 t; cvta.to.shared.u64 t, %1; cvt.u32.u64 %0, t; }" : "=r"(a) : "l"(p));
    return a;
}
__device__ __forceinline__ void ldsm4t(uint32_t* r, uint32_t addr) {
    asm volatile("ldmatrix.sync.aligned.m8n8.x4.trans.shared.b16 {%0,%1,%2,%3}, [%4];"
                 : "=r"(r[0]), "=r"(r[1]), "=r"(r[2]), "=r"(r[3]) : "r"(addr));
}
__device__ __forceinline__ void mma16816(float* c, const uint32_t* a, const uint32_t* b) {
    asm volatile("mma.sync.aligned.m16n8k16.row.col.f32.bf16.bf16.f32 "
                 "{%0,%1,%2,%3}, {%4,%5,%6,%7}, {%8,%9}, {%0,%1,%2,%3};"
                 : "+f"(c[0]), "+f"(c[1]), "+f"(c[2]), "+f"(c[3])
                 : "r"(a[0]), "r"(a[1]), "r"(a[2]), "r"(a[3]), "r"(b[0]), "r"(b[1]));
}

// ---- prep: M -> bf16 + ||m||^2, 16 blocks x 32 k-cols ----
__global__ __launch_bounds__(256) void k_prep(const float* __restrict__ M) {
    __shared__ float part[8][32];
    const int kl = threadIdx.x & 31;             // k within block's 32 columns
    const int dg = threadIdx.x >> 5;             // d-group 0..7 (32 d each)
    const int k  = blockIdx.x * 32 + kl;
    float s = 0.f;
    #pragma unroll 8
    for (int i = 0; i < 32; ++i) {
        int d = dg * 32 + i;
        float v = M[(size_t)d * Kn + k];
        g_Mc[(size_t)d * Kn + k] = __float2bfloat16(v);
        s = fmaf(v, v, s);
    }
    part[dg][kl] = s;
    __syncthreads();
    if (dg == 0) {
        float t = 0.f;
        #pragma unroll
        for (int i = 0; i < 8; ++i) t += part[i][kl];
        g_mnorm[k] = t;
    }
}

// ---- main: 128 GEMM CTAs + 20 reduction CTAs, shared ticket ----
__global__ __launch_bounds__(256, 1) void k_mma(const float* __restrict__ H,
                                                const float* __restrict__ Xhat,
                                                const float* __restrict__ X,
                                                const float* __restrict__ Dh,
                                                float* out) {
    extern __shared__ char sm[];
    const uint32_t sb = smem_u32(sm);
    const int tid = threadIdx.x, w = tid >> 5, ln = tid & 31;

    if (blockIdx.x >= 128) {
        // -------- reduction CTAs on otherwise-idle SMs --------
        int which, n, b0, nb;
        const float* a; const float* bp;
        if (blockIdx.x < 146) { which = 0; a = Xhat; bp = X; n = N_REC;  b0 = 128; nb = 18; }
        else                  { which = 2; a = Dh;   bp = 0; n = N_DHAT; b0 = 146; nb = 2;  }
        float s = 0.f;
        for (int i = ((int)blockIdx.x - b0) * 256 + tid; i < n; i += nb * 256) {
            if (which == 0) { float d = a[i] - bp[i]; s = fmaf(d, d, s); }
            else            { s += a[i]; }
        }
        #pragma unroll
        for (int o = 16; o; o >>= 1) s += __shfl_down_sync(0xffffffffu, s, o);
        float* ws = (float*)(sm + SRED);
        if (!ln) ws[w] = s;
        __syncthreads();
        if (tid == 0) {
            float t = 0.f;
            #pragma unroll
            for (int i = 0; i < 8; ++i) t += ws[i];
            atomicAdd(&g_acc[which], (double)t);
        }
    } else {
        // -------- GEMM CTA: 256 rows x 512 cols (R7 config) --------
        const int row0 = blockIdx.x * 256;
        const int b = row0 >> 9, t0 = row0 & 511;          // t0 in {0, 256}

        ((float*)(sm + SMNS))[tid]       = g_mnorm[tid];
        ((float*)(sm + SMNS))[tid + 256] = g_mnorm[tid + 256];

        const size_t gmc = __cvta_generic_to_global((const void*)g_Mc);
        auto cp_chunk = [&](int c, uint32_t dstoff) {       // 64-col chunk: 256 rows * 128B
            #pragma unroll
            for (int i = 0; i < 8; ++i) {
                int u = tid + 256 * i;                      // 0..2047 16B units
                int d = u >> 3, seg = u & 7;
                uint32_t dst = sb + dstoff + d * BP + seg * 16;
                size_t   src = gmc + (size_t)d * 1024 + (size_t)c * 128 + seg * 16;
                asm volatile("cp.async.cg.shared.global [%0], [%1], 16;" :: "r"(dst), "l"(src));
            }
            asm volatile("cp.async.commit_group;" ::: "memory");
        };
        cp_chunk(0, SB0);
        cp_chunk(1, SB1);

        // Stage A: H[b][d][t0..t0+255] fp32 -> bf16 smem [d][t]; accumulate sum(H^2).
        float sq = 0.f;
        const float* Hp = H + (size_t)b * Dn * Tn + t0;
        #pragma unroll
        for (int i = 0; i < 64; ++i) {
            int u = tid + 256 * i;                 // 0..16383 float4 units
            int d = u >> 6, seg = u & 63;
            float4 v = *(const float4*)(Hp + (size_t)d * Tn + seg * 4);
            sq = fmaf(v.x, v.x, fmaf(v.y, v.y, fmaf(v.z, v.z, fmaf(v.w, v.w, sq))));
            __nv_bfloat162 p0 = __floats2bfloat162_rn(v.x, v.y);
            __nv_bfloat162 p1 = __floats2bfloat162_rn(v.z, v.w);
            uint32_t a = sb + SA + d * AP + seg * 8;
            asm volatile("st.shared.v2.b32 [%0], {%1,%2};"
                         :: "r"(a), "r"(*(uint32_t*)&p0), "r"(*(uint32_t*)&p1) : "memory");
        }
        #pragma unroll
        for (int o = 16; o; o >>= 1) sq += __shfl_down_sync(0xffffffffu, sq, o);
        if (!ln) ((float*)(sm + SRED))[w] = sq;

        // 8 warps: 4 (m) x 2 (n). Warp tile per chunk: 64 rows x 32 cols.
        const int wm  = (w & 3) * 64;
        const int wn  = (w >> 2) * 32;
        const int s1  = ((ln >> 3) & 1) * 8;
        const int s2  = (ln >> 4) * 8;
        const int r8  = ln & 7;
        const float* mns = (const float*)(sm + SMNS);

        float rm[8];
        #pragma unroll
        for (int i = 0; i < 8; ++i) rm[i] = 3.4e38f;

        for (int c = 0; c < 8; ++c) {
            asm volatile("cp.async.wait_group 1;" ::: "memory");   // chunk c resident
            __syncthreads();
            const uint32_t bb = sb + ((c & 1) ? SB1 : SB0);

            float acc[4][4][4];
            #pragma unroll
            for (int mf = 0; mf < 4; ++mf)
                #pragma unroll
                for (int nf = 0; nf < 4; ++nf)
                    #pragma unroll
                    for (int j = 0; j < 4; ++j) acc[mf][nf][j] = 0.f;

            #pragma unroll
            for (int ks = 0; ks < 16; ++ks) {
                const int d0 = ks * 16;
                uint32_t af[4][4], bf[2][4];
                #pragma unroll
                for (int np = 0; np < 2; ++np)
                    ldsm4t(bf[np], bb + (d0 + s1 + r8) * BP + (wn + np * 16 + s2) * 2);
                #pragma unroll
                for (int mf = 0; mf < 4; ++mf)
                    ldsm4t(af[mf], sb + SA + (d0 + s2 + r8) * AP + (wm + mf * 16 + s1) * 2);
                #pragma unroll
                for (int mf = 0; mf < 4; ++mf)
                    #pragma unroll
                    for (int nf = 0; nf < 4; ++nf)
                        mma16816(acc[mf][nf], af[mf], &bf[nf >> 1][(nf & 1) * 2]);
            }

            const int cb = c * 64 + wn + 2 * (ln & 3);
            #pragma unroll
            for (int nf = 0; nf < 4; ++nf) {
                float m0 = mns[cb + nf * 8], m1 = mns[cb + nf * 8 + 1];
                #pragma unroll
                for (int mf = 0; mf < 4; ++mf) {
                    rm[mf * 2]     = fminf(rm[mf * 2],
                        fminf(fmaf(-2.f, acc[mf][nf][0], m0), fmaf(-2.f, acc[mf][nf][1], m1)));
                    rm[mf * 2 + 1] = fminf(rm[mf * 2 + 1],
                        fminf(fmaf(-2.f, acc[mf][nf][2], m0), fmaf(-2.f, acc[mf][nf][3], m1)));
                }
            }

            if (c < 6) {
                __syncthreads();                    // all warps done reading buffer (c&1)
                cp_chunk(c + 2, (c & 1) ? SB1 : SB0);
            }
        }

        // combine 4 lanes sharing each row
        #pragma unroll
        for (int o = 1; o < 4; o <<= 1) {
            #pragma unroll
            for (int i = 0; i < 8; ++i) rm[i] = fminf(rm[i], __shfl_xor_sync(0xffffffffu, rm[i], o));
        }
        if ((ln & 3) == 0) {
            float* rmin = (float*)(sm + SRMIN) + (w >> 2) * 256;
            int r = wm + (ln >> 2);
            #pragma unroll
            for (int mf = 0; mf < 4; ++mf) {
                rmin[r + mf * 16]     = rm[mf * 2];
                rmin[r + mf * 16 + 8] = rm[mf * 2 + 1];
            }
        }
        __syncthreads();

        {   // combine n-groups, sum rows
            const float* r0 = (const float*)(sm + SRMIN);
            double s = (double)fminf(r0[tid], r0[tid + 256]);
            #pragma unroll
            for (int o = 16; o; o >>= 1) s += __shfl_down_sync(0xffffffffu, s, o);
            if (!ln) ((double*)(sm + SRED + 64))[w] = s;
        }
        __syncthreads();

        if (tid == 0) {
            const double* dr = (const double*)(sm + SRED + 64);
            double ms = 0.0;
            #pragma unroll
            for (int i = 0; i < 8; ++i) ms += dr[i];
            atomicAdd(&g_acc[1], ms);
            const float* ws = (const float*)(sm + SRED);
            double hs = 0.0;
            #pragma unroll
            for (int i = 0; i < 8; ++i) hs += (double)ws[i];
            atomicAdd(&g_acc[3], hs);
        }
    }

    // -------- shared ticketed finalize (all 148 CTAs) --------
    if (tid == 0) {
        __threadfence();
        unsigned old = atomicAdd(&g_ticket, 1u);
        if (old == gridDim.x - 1) {
            __threadfence();
            double a0 = *(volatile double*)&g_acc[0];
            double a1 = *(volatile double*)&g_acc[1];
            double a2 = *(volatile double*)&g_acc[2];
            double a3 = *(volatile double*)&g_acc[3];
            double mem = 2.0 * (a3 + a1) / (double)((size_t)Bn * Dn * Tn);
            out[0] = (float)(a0 / (double)N_REC + 0.25 * mem - 0.1 * a2 / (double)N_DHAT);
            g_acc[0] = 0.0; g_acc[1] = 0.0; g_acc[2] = 0.0; g_acc[3] = 0.0;
            g_ticket = 0u;
            __threadfence();
        }
    }
}

extern "C" void kernel_launch(void* const* d_in, const int* in_sizes, int n_in,
                              void* d_out, int out_size) {
    (void)in_sizes; (void)n_in; (void)out_size;
    const float* Xhat = (const float*)d_in[0];
    const float* X    = (const float*)d_in[1];
    const float* H    = (const float*)d_in[2];
    const float* M    = (const float*)d_in[3];
    const float* Dh   = (const float*)d_in[4];

    cudaFuncSetAttribute(k_mma, cudaFuncAttributeMaxDynamicSharedMemorySize, SMEMT);

    k_prep<<<16, 256>>>(M);
    k_mma<<<148, 256, SMEMT>>>(H, Xhat, X, Dh, (float*)d_out);
}